// round 14
// baseline (speedup 1.0000x reference)
#include <cuda_runtime.h>
#include <cuda_bf16.h>
#include <cstdint>

#define THREADS 512
#define GRID 152          // persistent: one CTA per SM
#define BM 64             // edges per tile
#define HID 256
#define INCH 256
#define NQ 4              // K quarters of 64

// ---- dynamic smem layout (bytes) ----
#define AHI(p)    ((p) * 8192)        // A hi, 64 rows x 128B, double buffered
#define B_OFF     16384               // 256 rows x 512B (XOR-swizzled)
#define SB1_OFF   147456
#define SW2_OFF   148480
#define IDX_OFF   149504              // set p: src[64] @ p*512, dst[64] @ +256
#define SPART_OFF 150528              // 64 rows x 8 wn x f32 = 2 KB
#define SMEM_DYN  152576

__device__ __nv_bfloat16 g_W1T_hi[HID * INCH];   // K-major [n][k]

__global__ void prep_w1(const float* __restrict__ W1) {
    int k = blockIdx.x;
    int n = threadIdx.x;
    g_W1T_hi[n * INCH + k] = __float2bfloat16(W1[k * HID + n]);
}

static __device__ __forceinline__ void mma16816(float* d, const uint32_t* a,
                                                uint32_t b0, uint32_t b1) {
    asm volatile(
        "mma.sync.aligned.m16n8k16.row.col.f32.bf16.bf16.f32 "
        "{%0,%1,%2,%3},{%4,%5,%6,%7},{%8,%9},{%0,%1,%2,%3};"
        : "+f"(d[0]), "+f"(d[1]), "+f"(d[2]), "+f"(d[3])
        : "r"(a[0]), "r"(a[1]), "r"(a[2]), "r"(a[3]), "r"(b0), "r"(b1));
}

__global__ void __launch_bounds__(THREADS, 1)
edge_decoder_w16(const float* __restrict__ z,
                 const int* __restrict__ src,
                 const int* __restrict__ dst,
                 const float* __restrict__ b1,
                 const float* __restrict__ W2,
                 const float* __restrict__ b2,
                 float* __restrict__ out,
                 int E, int Nn, int NT)
{
    extern __shared__ __align__(16) char sm[];
    const int tid  = threadIdx.x;
    const int lane = tid & 31;
    const int wid  = tid >> 5;       // 0..15
    const int wm   = wid & 1;        // M half: rows wm*32..+32
    const int wn   = wid >> 1;       // N eighth: cols wn*32..+32
    const int g    = lane >> 2;
    const int c4   = (lane & 3) << 2;
    const int sw   = g << 4;
    const int rowbase = tid >> 4;    // convert row base 0..31
    const int klel    = (tid & 15) << 2;   // element offset within quarter

    float* s_b1 = (float*)(sm + SB1_OFF);
    float* s_w2 = (float*)(sm + SW2_OFF);

    // ---------- prologue ----------
    // resident B (XOR-swizzled 512B rows): 8192 x 16B, 16 per thread
    {
        const char* gH = (const char*)g_W1T_hi;
        #pragma unroll
        for (int j = 0; j < 16; j++) {
            int q = tid + j * THREADS;
            int n = q >> 5;
            int c16 = (q & 31) << 4;
            *(uint4*)(sm + B_OFF + n * 512 + (c16 ^ ((n & 7) << 4))) =
                *(const uint4*)(gH + n * 512 + c16);
        }
    }
    if (tid < 128) {
        int row = tid & 63;
        long long e = (long long)blockIdx.x * BM + row;
        if (e >= E) e = E - 1;
        int v = (tid < 64) ? src[e] : dst[e];
        v = (v < 0) ? 0 : (v >= Nn ? Nn - 1 : v);
        ((int*)(sm + IDX_OFF + ((tid < 64) ? 0 : 256)))[row] = v * INCH;
    }
    if (tid < 256) {
        s_b1[tid] = b1[tid];
        s_w2[tid] = W2[tid];
    }
    const float bias2 = b2[0];
    __syncthreads();

    // register staging: 2 rows per thread (src+dst float4)
    float4 zs[2], zd[2];

    // LDG q0 -> regs; convert -> A[0]; LDG q1 -> regs
    {
        const int* ssrc = (const int*)(sm + IDX_OFF);
        const int* sdst = ssrc + 64;
        #pragma unroll
        for (int j = 0; j < 2; j++) {
            int m = rowbase + j * 32;
            zs[j] = *(const float4*)(z + ssrc[m] + klel);          // q0
            zd[j] = *(const float4*)(z + sdst[m] + klel);
        }
        #pragma unroll
        for (int j = 0; j < 2; j++) {
            int m = rowbase + j * 32;
            __nv_bfloat162 h01 = __floats2bfloat162_rn(zs[j].x * zd[j].x, zs[j].y * zd[j].y);
            __nv_bfloat162 h23 = __floats2bfloat162_rn(zs[j].z * zd[j].z, zs[j].w * zd[j].w);
            uint2 hv;
            hv.x = *(uint32_t*)&h01; hv.y = *(uint32_t*)&h23;
            int off = m * 128 + ((klel * 2) ^ ((m & 7) << 4));
            *(uint2*)(sm + AHI(0) + off) = hv;
        }
        #pragma unroll
        for (int j = 0; j < 2; j++) {
            int m = rowbase + j * 32;
            zs[j] = *(const float4*)(z + ssrc[m] + 64 + klel);     // q1
            zd[j] = *(const float4*)(z + sdst[m] + 64 + klel);
        }
    }

    // ---------- pipelined persistent loop ----------
    int it = 0;
    for (int i = blockIdx.x; i < NT; i += GRID, it++) {
        float acc[2][4][4];
        #pragma unroll
        for (int mt = 0; mt < 2; mt++)
            #pragma unroll
            for (int nt = 0; nt < 4; nt++)
                #pragma unroll
                for (int k = 0; k < 4; k++) acc[mt][nt][k] = 0.f;

        #pragma unroll
        for (int h = 0; h < NQ; h++) {
            __syncthreads();   // A[h&1] visible; A[(h+1)&1] free; s_part free at h=0

            if (h == 1 && tid < 128) {      // prefetch idx(it+1) -> set (it+1)&1
                int row = tid & 63;
                long long e = ((long long)i + GRID) * BM + row;
                if (e >= E) e = E - 1;
                int v = (tid < 64) ? src[e] : dst[e];
                v = (v < 0) ? 0 : (v >= Nn ? Nn - 1 : v);
                ((int*)(sm + IDX_OFF + ((it + 1) & 1) * 512 + ((tid < 64) ? 0 : 256)))[row] = v * INCH;
            }

            // ---- MMA quarter h from A[h&1] ----
            const int ahi = AHI(h & 1);
            #pragma unroll
            for (int ks = 0; ks < 4; ks++) {
                const int kb = ks * 32;
                const int o0 = (kb ^ sw) + c4;
                const int o1 = ((kb + 16) ^ sw) + c4;
                uint32_t ah[2][4];
                #pragma unroll
                for (int mt = 0; mt < 2; mt++) {
                    const int rb = (wm * 32 + mt * 16 + g) * 128;
                    ah[mt][0] = *(const uint32_t*)(sm + ahi + rb + o0);
                    ah[mt][1] = *(const uint32_t*)(sm + ahi + rb + o0 + 1024);
                    ah[mt][2] = *(const uint32_t*)(sm + ahi + rb + o1);
                    ah[mt][3] = *(const uint32_t*)(sm + ahi + rb + o1 + 1024);
                }
                #pragma unroll
                for (int nt = 0; nt < 4; nt++) {
                    const int nrow = (wn * 32 + nt * 8 + g) * 512 + c4;
                    const int kc = h * 128 + kb;
                    uint32_t b0 = *(const uint32_t*)(sm + B_OFF + nrow + (kc ^ sw));
                    uint32_t b1r = *(const uint32_t*)(sm + B_OFF + nrow + ((kc + 16) ^ sw));
                    mma16816(acc[0][nt], ah[0], b0, b1r);
                    mma16816(acc[1][nt], ah[1], b0, b1r);
                }
            }

            // ---- convert staged regs (quarter h+1) -> A[(h+1)&1] ----
            {
                const int adst = AHI((h + 1) & 1);
                #pragma unroll
                for (int j = 0; j < 2; j++) {
                    int m = rowbase + j * 32;
                    __nv_bfloat162 h01 = __floats2bfloat162_rn(zs[j].x * zd[j].x, zs[j].y * zd[j].y);
                    __nv_bfloat162 h23 = __floats2bfloat162_rn(zs[j].z * zd[j].z, zs[j].w * zd[j].w);
                    uint2 hv;
                    hv.x = *(uint32_t*)&h01; hv.y = *(uint32_t*)&h23;
                    int off = m * 128 + ((klel * 2) ^ ((m & 7) << 4));
                    *(uint2*)(sm + adst + off) = hv;
                }
            }

            // ---- issue LDG for quarter h+2 (lands during next phase's MMA) ----
            {
                int qk  = (h + 2) & 3;
                int set = (h >= 2) ? ((it + 1) & 1) : (it & 1);
                const int* ssrc = (const int*)(sm + IDX_OFF + set * 512);
                const int* sdst = ssrc + 64;
                #pragma unroll
                for (int j = 0; j < 2; j++) {
                    int m = rowbase + j * 32;
                    zs[j] = *(const float4*)(z + ssrc[m] + qk * 64 + klel);
                    zd[j] = *(const float4*)(z + sdst[m] + qk * 64 + klel);
                }
            }
        }

        // ---------- fused epilogue (tile i) ----------
        float pr[2][2];
        #pragma unroll
        for (int mt = 0; mt < 2; mt++) {
            float p0 = 0.f, p1 = 0.f;
            #pragma unroll
            for (int nt = 0; nt < 4; nt++) {
                int c0 = wn * 32 + nt * 8 + (lane & 3) * 2;
                float w2a = s_w2[c0],     b1a = s_b1[c0];
                float w2b = s_w2[c0 + 1], b1b = s_b1[c0 + 1];
                p0 = fmaf(fmaxf(acc[mt][nt][0] + b1a, 0.f), w2a, p0);
                p0 = fmaf(fmaxf(acc[mt][nt][1] + b1b, 0.f), w2b, p0);
                p1 = fmaf(fmaxf(acc[mt][nt][2] + b1a, 0.f), w2a, p1);
                p1 = fmaf(fmaxf(acc[mt][nt][3] + b1b, 0.f), w2b, p1);
            }
            p0 += __shfl_xor_sync(0xffffffffu, p0, 1);
            p0 += __shfl_xor_sync(0xffffffffu, p0, 2);
            p1 += __shfl_xor_sync(0xffffffffu, p1, 1);
            p1 += __shfl_xor_sync(0xffffffffu, p1, 2);
            pr[mt][0] = p0; pr[mt][1] = p1;
        }

        float* s_part = (float*)(sm + SPART_OFF);   // [64][8]
        if ((lane & 3) == 0) {
            #pragma unroll
            for (int mt = 0; mt < 2; mt++) {
                int r = wm * 32 + mt * 16 + g;
                s_part[r * 8 + wn]       = pr[mt][0];
                s_part[(r + 8) * 8 + wn] = pr[mt][1];
            }
        }
        __syncthreads();
        if (tid < BM) {
            float p = 0.f;
            #pragma unroll
            for (int k = 0; k < 8; k++) p += s_part[tid * 8 + k];
            long long e = (long long)i * BM + tid;
            if (e < E)
                out[e] = 1.f / (1.f + __expf(-(p + bias2)));
        }
        // next tile's h=0 top sync orders s_part reuse
    }
}

extern "C" void kernel_launch(void* const* d_in, const int* in_sizes, int n_in,
                              void* d_out, int out_size) {
    // size-based input mapping (dict order confirmed: z,src,dst,W1,b1,W2,b2)
    int idx_z = -1, idx_w1 = -1, idx_b2 = -1;
    int idx_e1 = -1, idx_e2 = -1, idx_s1 = -1, idx_s2 = -1;
    for (int i = 0; i < n_in; i++) {
        int s = in_sizes[i];
        if (s == 25600000)      idx_z = i;
        else if (s == 65536)    idx_w1 = i;
        else if (s == 1)        idx_b2 = i;
        else if (s == 1000000) { if (idx_e1 < 0) idx_e1 = i; else idx_e2 = i; }
        else if (s == 256)     { if (idx_s1 < 0) idx_s1 = i; else idx_s2 = i; }
    }
    int idx_b1 = (idx_z == 0) ? idx_s1 : idx_s2;
    int idx_w2 = (idx_z == 0) ? idx_s2 : idx_s1;

    const float* z   = (const float*)d_in[idx_z];
    const int*   src = (const int*)d_in[idx_e1];
    const int*   dst = (const int*)d_in[idx_e2];
    const float* W1  = (const float*)d_in[idx_w1];
    const float* b1  = (const float*)d_in[idx_b1];
    const float* W2  = (const float*)d_in[idx_w2];
    const float* b2  = (const float*)d_in[idx_b2];
    float* out = (float*)d_out;

    int E  = in_sizes[idx_e1];
    int Nn = in_sizes[idx_z] / INCH;
    int NT = (E + BM - 1) / BM;     // 15625

    prep_w1<<<INCH, HID>>>(W1);

    static int smem_set = 0;
    if (!smem_set) {
        cudaFuncSetAttribute(edge_decoder_w16,
                             cudaFuncAttributeMaxDynamicSharedMemorySize, SMEM_DYN);
        smem_set = 1;
    }
    edge_decoder_w16<<<GRID, THREADS, SMEM_DYN>>>(z, src, dst, b1, W2, b2,
                                                  out, E, Nn, NT);
}